// round 9
// baseline (speedup 1.0000x reference)
#include <cuda_runtime.h>
#include <cuda_bf16.h>
#include <cstdint>

// ---------------- problem constants ----------------
#define N_NODES  50000
#define N_EDGES  400000
#define IN_F     128
#define HEADS    4
#define DIM      64
#define HD       256           // HEADS*DIM
#define NGRAPHS  2000
#define NEG_SLOPE 0.2f
#define SCAN_NB  196           // ceil(50000/256)
#define KEXT     384           // 3 * IN_F (bf16 split terms)
#define MBLK     391           // gemm blocks
#define HBLK     96            // histogram specialist blocks

// ---------------- device scratch ----------------
__device__ float g_fs[(size_t)N_NODES * HD];
__device__ float g_fd[(size_t)N_NODES * HD];
__device__ float g_e [(size_t)N_EDGES * HEADS];
__device__ float g_m [N_NODES * HEADS];
__device__ float g_den[N_NODES * HEADS];
__device__ float g_hsum[NGRAPHS * DIM];
__device__ float g_cnt [NGRAPHS];
__device__ int   g_deg[N_NODES];
__device__ int   g_cur[N_NODES];
__device__ int   g_off[N_NODES];
__device__ int2  g_epack[N_EDGES];        // {edge_id, src}
__device__ int   g_blksum[SCAN_NB];
__device__ __align__(16) __nv_bfloat16 g_Bext[2 * KEXT * HD];

__device__ __forceinline__ float lrelu(float x) {
    return x > 0.0f ? x : NEG_SLOPE * x;
}

__device__ __forceinline__ uint32_t smem_u32(const void* p) {
    uint32_t a;
    asm("{ .reg .u64 t; cvta.to.shared.u64 t, %1; cvt.u32.u64 %0, t; }" : "=r"(a) : "l"(p));
    return a;
}

// A smem: 128 rows x 256 bf16 cols (hi | lo), 512 B/row
__device__ __forceinline__ uint32_t a_off(int r, int c) {
    int chunk = (c >> 3) ^ (r & 7);
    return (uint32_t)r * 512u + (uint32_t)chunk * 16u + (uint32_t)(c & 7) * 2u;
}
// B smem: 32 k-rows x 256 bf16 cols, 512 B/row
__device__ __forceinline__ uint32_t b_off(int k, int n) {
    int chunk = (n >> 3) ^ (k & 7);
    return (uint32_t)k * 512u + (uint32_t)chunk * 16u + (uint32_t)(n & 7) * 2u;
}

// ---------------- fused prologue: zero scratch + build B_ext ----------------
__global__ __launch_bounds__(256) void k_pre(
    const float* __restrict__ Wsrc, const float* __restrict__ Wdst)
{
    int i = blockIdx.x * blockDim.x + threadIdx.x;
    int stride = gridDim.x * blockDim.x;
    for (int j = i; j < NGRAPHS * DIM; j += stride) g_hsum[j] = 0.0f;
    for (int j = i; j < NGRAPHS; j += stride) g_cnt[j] = 0.0f;
    for (int j = i; j < N_NODES; j += stride) { g_deg[j] = 0; g_cur[j] = 0; }
    for (int j = i; j < 2 * KEXT * HD; j += stride) {
        int mat  = j / (KEXT * HD);
        int r    = j % (KEXT * HD);
        int kext = r >> 8;
        int n    = r & 255;
        int k    = (kext < 2 * IN_F) ? (kext & (IN_F - 1)) : (kext - 2 * IN_F);
        const float* W = mat ? Wdst : Wsrc;
        float v = W[(size_t)k * HD + n];
        __nv_bfloat16 hi = __float2bfloat16(v);
        g_Bext[j] = (kext < 2 * IN_F) ? hi : __float2bfloat16(v - __bfloat162float(hi));
    }
}

// ---------------- bf16 mma.sync GEMM + fused dst histogram ----------------
// grid = MBLK + HBLK; blocks >= MBLK do the edge histogram (runs concurrently)
#define SM_A_BYTES 65536
#define SM_B_BYTES 16384
#define SM_TOT (SM_A_BYTES + SM_B_BYTES)

__global__ __launch_bounds__(512) void k_mgemm(
    const float* __restrict__ atom,
    const float* __restrict__ bsrc, const float* __restrict__ bdst,
    const int* __restrict__ dst)
{
    extern __shared__ char smem[];
    const int tid  = threadIdx.x;

    if (blockIdx.x >= MBLK) {          // histogram specialist blocks
        int t = (blockIdx.x - MBLK) * 512 + tid;
        for (int e = t; e < N_EDGES; e += HBLK * 512)
            atomicAdd(&g_deg[dst[e]], 1);
        return;
    }

    const uint32_t sA = smem_u32(smem);
    const uint32_t sB = sA + SM_A_BYTES;

    const int lane = tid & 31;
    const int wid  = tid >> 5;             // 0..15
    const int row0 = blockIdx.x * 128;

    // ---- A: load 128 rows x 128 fp32 once, hi/lo bf16 into smem ----
    {
        int ar = tid >> 2;                 // 0..127
        int c0 = (tid & 3) * 32;
        bool valid = (row0 + ar) < N_NODES;
        const float4* arow = (const float4*)(atom + (size_t)(row0 + ar) * IN_F + c0);
#pragma unroll
        for (int i = 0; i < 8; i++) {
            float4 v = valid ? arow[i] : make_float4(0.f, 0.f, 0.f, 0.f);
            int c = c0 + i * 4;
            __nv_bfloat162 h0 = __float22bfloat162_rn(make_float2(v.x, v.y));
            __nv_bfloat162 h1 = __float22bfloat162_rn(make_float2(v.z, v.w));
            float2 f0 = __bfloat1622float2(h0);
            float2 f1 = __bfloat1622float2(h1);
            __nv_bfloat162 l0 = __float22bfloat162_rn(make_float2(v.x - f0.x, v.y - f0.y));
            __nv_bfloat162 l1 = __float22bfloat162_rn(make_float2(v.z - f1.x, v.w - f1.y));
            uint2 hp, lp;
            hp.x = *(uint32_t*)&h0; hp.y = *(uint32_t*)&h1;
            lp.x = *(uint32_t*)&l0; lp.y = *(uint32_t*)&l1;
            *(uint2*)(smem + a_off(ar, c))       = hp;
            *(uint2*)(smem + a_off(ar, 128 + c)) = lp;
        }
    }

    const int wr = wid >> 2;               // 0..3
    const int wc = wid & 3;                // 0..3
    const int mbase = wr * 32;
    const int nbase = wc * 64;

    const int kr = tid >> 4;               // 0..31
    const int ch = tid & 15;               // 0..15
    const uint32_t bso0 = SM_A_BYTES + b_off(kr, ch * 8);
    const uint32_t bso1 = SM_A_BYTES + b_off(kr, 128 + ch * 8);

    const int a_r  = lane & 15;
    const int a_c8 = (lane >> 4) << 3;
    const int b_kr = (lane & 7) + (((lane >> 3) & 1) << 3);
    const int b_n8 = (lane >> 4) << 3;

    const int g  = lane >> 2;
    const int tg = lane & 3;

    for (int mat = 0; mat < 2; mat++) {
        const __nv_bfloat16* Bg = g_Bext + (size_t)mat * KEXT * HD;

        float acc[2][8][4];
#pragma unroll
        for (int a = 0; a < 2; a++)
#pragma unroll
            for (int b = 0; b < 8; b++)
#pragma unroll
                for (int c = 0; c < 4; c++) acc[a][b][c] = 0.0f;

        uint4 pv0 = *(const uint4*)(Bg + (size_t)kr * HD + ch * 8);
        uint4 pv1 = *(const uint4*)(Bg + (size_t)kr * HD + 128 + ch * 8);

        for (int it = 0; it < 12; it++) {
            __syncthreads();
            *(uint4*)(smem + bso0) = pv0;
            *(uint4*)(smem + bso1) = pv1;
            __syncthreads();

            if (it < 11) {
                const __nv_bfloat16* brow = Bg + (size_t)((it + 1) * 32 + kr) * HD;
                pv0 = *(const uint4*)(brow + ch * 8);
                pv1 = *(const uint4*)(brow + 128 + ch * 8);
            }

            const int kk = it * 32;
            const int term = kk >> 7;
            const int acolb = (term == 1) ? (128 + (kk & 127)) : (kk & 127);

#pragma unroll
            for (int ks = 0; ks < 32; ks += 16) {
                uint32_t af[2][4];
#pragma unroll
                for (int mi = 0; mi < 2; mi++) {
                    uint32_t addr = sA + a_off(mbase + mi * 16 + a_r, acolb + ks + a_c8);
                    asm volatile("ldmatrix.sync.aligned.m8n8.x4.shared.b16 {%0,%1,%2,%3}, [%4];"
                                 : "=r"(af[mi][0]), "=r"(af[mi][1]), "=r"(af[mi][2]), "=r"(af[mi][3])
                                 : "r"(addr));
                }
                uint32_t bf[4][4];
#pragma unroll
                for (int ni = 0; ni < 4; ni++) {
                    uint32_t addr = sB + b_off(ks + b_kr, nbase + ni * 16 + b_n8);
                    asm volatile("ldmatrix.sync.aligned.m8n8.x4.trans.shared.b16 {%0,%1,%2,%3}, [%4];"
                                 : "=r"(bf[ni][0]), "=r"(bf[ni][1]), "=r"(bf[ni][2]), "=r"(bf[ni][3])
                                 : "r"(addr));
                }
#pragma unroll
                for (int mi = 0; mi < 2; mi++)
#pragma unroll
                    for (int ni = 0; ni < 4; ni++) {
                        asm volatile(
                            "mma.sync.aligned.m16n8k16.row.col.f32.bf16.bf16.f32 "
                            "{%0,%1,%2,%3}, {%4,%5,%6,%7}, {%8,%9}, {%0,%1,%2,%3};"
                            : "+f"(acc[mi][ni*2][0]), "+f"(acc[mi][ni*2][1]),
                              "+f"(acc[mi][ni*2][2]), "+f"(acc[mi][ni*2][3])
                            : "r"(af[mi][0]), "r"(af[mi][1]), "r"(af[mi][2]), "r"(af[mi][3]),
                              "r"(bf[ni][0]), "r"(bf[ni][1]));
                        asm volatile(
                            "mma.sync.aligned.m16n8k16.row.col.f32.bf16.bf16.f32 "
                            "{%0,%1,%2,%3}, {%4,%5,%6,%7}, {%8,%9}, {%0,%1,%2,%3};"
                            : "+f"(acc[mi][ni*2+1][0]), "+f"(acc[mi][ni*2+1][1]),
                              "+f"(acc[mi][ni*2+1][2]), "+f"(acc[mi][ni*2+1][3])
                            : "r"(af[mi][0]), "r"(af[mi][1]), "r"(af[mi][2]), "r"(af[mi][3]),
                              "r"(bf[ni][2]), "r"(bf[ni][3]));
                    }
            }
        }

        const float* bias = mat ? bdst : bsrc;
        float* outp       = mat ? g_fd : g_fs;
#pragma unroll
        for (int mi = 0; mi < 2; mi++) {
#pragma unroll
            for (int n8 = 0; n8 < 8; n8++) {
                int colg = nbase + n8 * 8 + tg * 2;
                float b0 = __ldg(bias + colg);
                float b1 = __ldg(bias + colg + 1);
                int r1 = row0 + mbase + mi * 16 + g;
                int r2 = r1 + 8;
                if (r1 < N_NODES) {
                    float2 v = make_float2(acc[mi][n8][0] + b0, acc[mi][n8][1] + b1);
                    *(float2*)(outp + (size_t)r1 * HD + colg) = v;
                }
                if (r2 < N_NODES) {
                    float2 v = make_float2(acc[mi][n8][2] + b0, acc[mi][n8][3] + b1);
                    *(float2*)(outp + (size_t)r2 * HD + colg) = v;
                }
            }
        }
    }
}

// ---------------- scans (scan1 computes block totals; scanB does base + elem scan) ----------------
__global__ __launch_bounds__(256) void k_scan1() {
    __shared__ int sh[256];
    int i = blockIdx.x * 256 + threadIdx.x;
    int v = (i < N_NODES) ? g_deg[i] : 0;
    sh[threadIdx.x] = v;
    __syncthreads();
    for (int d = 1; d < 256; d <<= 1) {
        int t = (threadIdx.x >= d) ? sh[threadIdx.x - d] : 0;
        __syncthreads();
        sh[threadIdx.x] += t;
        __syncthreads();
    }
    if (threadIdx.x == 255) g_blksum[blockIdx.x] = sh[255];
}

__global__ __launch_bounds__(256) void k_scanB() {
    __shared__ int sh[256];
    __shared__ int wsum[8];
    __shared__ int base_s;
    int b = blockIdx.x;
    int t = threadIdx.x;

    // base = sum of blksum[0..b)
    int v = (t < b) ? g_blksum[t] : 0;
#pragma unroll
    for (int d = 16; d; d >>= 1) v += __shfl_down_sync(0xFFFFFFFFu, v, d);
    if ((t & 31) == 0) wsum[t >> 5] = v;
    __syncthreads();
    if (t == 0) {
        int s = 0;
#pragma unroll
        for (int j = 0; j < 8; j++) s += wsum[j];
        base_s = s;
    }
    __syncthreads();

    int i = b * 256 + t;
    int dv = (i < N_NODES) ? g_deg[i] : 0;
    sh[t] = dv;
    __syncthreads();
    for (int d = 1; d < 256; d <<= 1) {
        int x = (t >= d) ? sh[t - d] : 0;
        __syncthreads();
        sh[t] += x;
        __syncthreads();
    }
    if (i < N_NODES) g_off[i] = base_s + sh[t] - dv;
}

__global__ __launch_bounds__(256) void k_fill(
    const int* __restrict__ dst, const int* __restrict__ src)
{
    int e = blockIdx.x * blockDim.x + threadIdx.x;
    if (e >= N_EDGES) return;
    int d = dst[e];
    int pos = atomicAdd(&g_cur[d], 1);
    g_epack[g_off[d] + pos] = make_int2(e, src[e]);
}

// ---------------- fused per-node online-softmax aggregation (pairwise, pipelined) ----------------
__global__ __launch_bounds__(256) void k_agg(
    const float* __restrict__ attn,
    const int* __restrict__ gid, float* __restrict__ x1)
{
    int warp = (blockIdx.x * blockDim.x + threadIdx.x) >> 5;
    if (warp >= N_NODES) return;
    int n = warp;
    int lane = threadIdx.x & 31;
    int base = lane * 8;
    int h = lane >> 3;

    float4 fd0 = *(const float4*)(g_fd + (size_t)n * HD + base);
    float4 fd1 = *(const float4*)(g_fd + (size_t)n * HD + base + 4);
    float4 aw0 = __ldg((const float4*)(attn + base));
    float4 aw1 = __ldg((const float4*)(attn + base + 4));

    int deg = g_deg[n];
    int off = g_off[n];
    int npairs = (deg + 1) >> 1;

    const float NEG_INF = __int_as_float(0xff800000);
    float m = NEG_INF;
    float den = 0.0f;
    float acc[8];
#pragma unroll
    for (int j = 0; j < 8; j++) acc[j] = 0.0f;

    int2 eA = make_int2(0, 0), eB = make_int2(0, 0);
    int2 nA = make_int2(0, 0), nB = make_int2(0, 0);
    float4 cA0, cA1, cB0, cB1;

    if (npairs > 0) {
        eA = g_epack[off];
        eB = (deg > 1) ? g_epack[off + 1] : eA;
        const float4* fA = (const float4*)(g_fs + (size_t)eA.y * HD + base);
        const float4* fB = (const float4*)(g_fs + (size_t)eB.y * HD + base);
        cA0 = fA[0]; cA1 = fA[1];
        cB0 = fB[0]; cB1 = fB[1];
        if (npairs > 1) {
            nA = g_epack[off + 2];
            nB = (deg > 3) ? g_epack[off + 3] : nA;
        }
    }

    for (int p = 0; p < npairs; p++) {
        bool hasB    = (2 * p + 1) < deg;
        bool hasNext = (p + 1) < npairs;

        // prefetch next pair's fs rows (addresses known from last iteration)
        float4 pA0, pA1, pB0, pB1;
        if (hasNext) {
            const float4* fA = (const float4*)(g_fs + (size_t)nA.y * HD + base);
            const float4* fB = (const float4*)(g_fs + (size_t)nB.y * HD + base);
            pA0 = fA[0]; pA1 = fA[1];
            pB0 = fB[0]; pB1 = fB[1];
        }
        // prefetch es for pair p+2
        int2 fA2 = nA, fB2 = nB;
        if (p + 2 < npairs) {
            fA2 = g_epack[off + 2 * p + 4];
            fB2 = (2 * p + 5 < deg) ? g_epack[off + 2 * p + 5] : fA2;
        }

        // logits for both edges (interleaved for ILP)
        float evA, evB;
        evA  = lrelu(cA0.x + fd0.x) * aw0.x;
        evB  = lrelu(cB0.x + fd0.x) * aw0.x;
        evA += lrelu(cA0.y + fd0.y) * aw0.y;
        evB += lrelu(cB0.y + fd0.y) * aw0.y;
        evA += lrelu(cA0.z + fd0.z) * aw0.z;
        evB += lrelu(cB0.z + fd0.z) * aw0.z;
        evA += lrelu(cA0.w + fd0.w) * aw0.w;
        evB += lrelu(cB0.w + fd0.w) * aw0.w;
        evA += lrelu(cA1.x + fd1.x) * aw1.x;
        evB += lrelu(cB1.x + fd1.x) * aw1.x;
        evA += lrelu(cA1.y + fd1.y) * aw1.y;
        evB += lrelu(cB1.y + fd1.y) * aw1.y;
        evA += lrelu(cA1.z + fd1.z) * aw1.z;
        evB += lrelu(cB1.z + fd1.z) * aw1.z;
        evA += lrelu(cA1.w + fd1.w) * aw1.w;
        evB += lrelu(cB1.w + fd1.w) * aw1.w;
#pragma unroll
        for (int d = 1; d < 8; d <<= 1) {
            evA += __shfl_xor_sync(0xFFFFFFFFu, evA, d);
            evB += __shfl_xor_sync(0xFFFFFFFFu, evB, d);
        }

        if ((lane & 7) == 0) {
            g_e[(size_t)eA.x * HEADS + h] = evA;
            if (hasB) g_e[(size_t)eB.x * HEADS + h] = evB;
        }

        float evB_eff = hasB ? evB : NEG_INF;
        float m_new = fmaxf(m, fmaxf(evA, evB_eff));
        float scale = __expf(m - m_new);
        float exA   = __expf(evA - m_new);
        float exB   = __expf(evB_eff - m_new);   // 0 when !hasB
        den = den * scale + exA + exB;
        acc[0] = acc[0] * scale + exA * cA0.x + exB * cB0.x;
        acc[1] = acc[1] * scale + exA * cA0.y + exB * cB0.y;
        acc[2] = acc[2] * scale + exA * cA0.z + exB * cB0.z;
        acc[3] = acc[3] * scale + exA * cA0.w + exB * cB0.w;
        acc[4] = acc[4] * scale + exA * cA1.x + exB * cB1.x;
        acc[5] = acc[5] * scale + exA * cA1.y + exB * cB1.y;
        acc[6] = acc[6] * scale + exA * cA1.z + exB * cB1.z;
        acc[7] = acc[7] * scale + exA * cA1.w + exB * cB1.w;
        m = m_new;

        if (hasNext) {
            eA = nA; eB = nB;
            cA0 = pA0; cA1 = pA1; cB0 = pB0; cB1 = pB1;
            nA = fA2; nB = fB2;
        }
    }

    if (deg > 0 && (lane & 7) == 0) {
        g_m  [n * HEADS + h] = m;
        g_den[n * HEADS + h] = den;
    }

    float inv = (den > 0.0f) ? (1.0f / den) : 0.0f;
    float r[8];
#pragma unroll
    for (int j = 0; j < 8; j++) {
        r[j] = acc[j] * inv;
        r[j] += __shfl_xor_sync(0xFFFFFFFFu, r[j], 8);
        r[j] += __shfl_xor_sync(0xFFFFFFFFu, r[j], 16);
        r[j] *= 0.25f;
    }

    int g = gid[n];
    if (lane < 8) {
        float4 v0 = make_float4(r[0], r[1], r[2], r[3]);
        float4 v1 = make_float4(r[4], r[5], r[6], r[7]);
        float* xp = x1 + (size_t)n * DIM + lane * 8;
        *(float4*)(xp)     = v0;
        *(float4*)(xp + 4) = v1;
        atomicAdd((float4*)(g_hsum + (size_t)g * DIM + lane * 8),     v0);
        atomicAdd((float4*)(g_hsum + (size_t)g * DIM + lane * 8 + 4), v1);
    }
    if (lane == 0) atomicAdd(&g_cnt[g], 1.0f);
}

// ---------------- score ----------------
__global__ __launch_bounds__(256) void k_score(
    const int* __restrict__ dst, float* __restrict__ score)
{
    int idx = blockIdx.x * blockDim.x + threadIdx.x;
    if (idx >= N_EDGES * HEADS) return;
    int e = idx >> 2, h = idx & 3;
    int d = dst[e];
    float alpha = __expf(g_e[idx] - g_m[d * HEADS + h]) / g_den[d * HEADS + h];
    score[idx] = alpha;
}

// ---------------- graph mean finalize ----------------
__global__ __launch_bounds__(256) void k_final(float* __restrict__ hout)
{
    int idx = blockIdx.x * blockDim.x + threadIdx.x;
    if (idx >= NGRAPHS * DIM) return;
    int g = idx >> 6;
    hout[idx] = g_hsum[idx] / fmaxf(g_cnt[g], 1.0f);
}

// ---------------- launcher ----------------
extern "C" void kernel_launch(void* const* d_in, const int* in_sizes, int n_in,
                              void* d_out, int out_size)
{
    (void)in_sizes; (void)n_in; (void)out_size;

    const float* atom = (const float*)d_in[0];
    const float* Wsrc = (const float*)d_in[1];
    const float* bsrc = (const float*)d_in[2];
    const float* Wdst = (const float*)d_in[3];
    const float* bdst = (const float*)d_in[4];
    const float* attn = (const float*)d_in[5];
    const int*   src  = (const int*)d_in[6];
    const int*   dst  = (const int*)d_in[7];
    const int*   gid  = (const int*)d_in[8];

    float* out   = (float*)d_out;
    float* x1    = out;
    float* hout  = out + (size_t)N_NODES * DIM;
    float* score = hout + (size_t)NGRAPHS * DIM;

    cudaFuncSetAttribute(k_mgemm, cudaFuncAttributeMaxDynamicSharedMemorySize, SM_TOT);

    k_pre<<<512, 256>>>(Wsrc, Wdst);                      // zero + B_ext

    k_mgemm<<<MBLK + HBLK, 512, SM_TOT>>>(atom, bsrc, bdst, dst);  // gemm + hist

    k_scan1<<<SCAN_NB, 256>>>();
    k_scanB<<<SCAN_NB, 256>>>();

    int eblocks = (N_EDGES + 255) / 256;
    k_fill<<<eblocks, 256>>>(dst, src);

    k_agg<<<(N_NODES * 32 + 255) / 256, 256>>>(attn, gid, x1);

    k_score<<<(N_EDGES * HEADS + 255) / 256, 256>>>(dst, score);

    k_final<<<(NGRAPHS * DIM + 255) / 256, 256>>>(hout);
}

// round 11
// speedup vs baseline: 1.0954x; 1.0954x over previous
#include <cuda_runtime.h>
#include <cuda_bf16.h>
#include <cstdint>

// ---------------- problem constants ----------------
#define N_NODES  50000
#define N_EDGES  400000
#define IN_F     128
#define HEADS    4
#define DIM      64
#define HD       256           // HEADS*DIM
#define NGRAPHS  2000
#define NEG_SLOPE 0.2f
#define SCAN_NB  196           // ceil(50000/256)
#define KEXT     384           // 3 * IN_F (bf16 split terms)
#define MBLK     391           // gemm blocks
#define HBLK     96            // histogram specialist blocks

// ---------------- device scratch ----------------
__device__ float g_fs[(size_t)N_NODES * HD];
__device__ float g_fd[(size_t)N_NODES * HD];
__device__ float g_e [(size_t)N_EDGES * HEADS];
__device__ float g_m [N_NODES * HEADS];
__device__ float g_den[N_NODES * HEADS];
__device__ float g_hsum[NGRAPHS * DIM];
__device__ float g_cnt [NGRAPHS];
__device__ int   g_deg[N_NODES];
__device__ int   g_cur[N_NODES];
__device__ int   g_off[N_NODES];
__device__ int2  g_epack[N_EDGES];        // {edge_id, src}
__device__ int   g_blksum[SCAN_NB];
__device__ __align__(16) __nv_bfloat16 g_Bext[2 * KEXT * HD];

__device__ __forceinline__ float lrelu(float x) {
    return x > 0.0f ? x : NEG_SLOPE * x;
}

__device__ __forceinline__ uint32_t smem_u32(const void* p) {
    uint32_t a;
    asm("{ .reg .u64 t; cvta.to.shared.u64 t, %1; cvt.u32.u64 %0, t; }" : "=r"(a) : "l"(p));
    return a;
}

// A smem: 128 rows x 256 bf16 cols (hi | lo), 512 B/row
__device__ __forceinline__ uint32_t a_off(int r, int c) {
    int chunk = (c >> 3) ^ (r & 7);
    return (uint32_t)r * 512u + (uint32_t)chunk * 16u + (uint32_t)(c & 7) * 2u;
}
// B smem: 32 k-rows x 256 bf16 cols, 512 B/row
__device__ __forceinline__ uint32_t b_off(int k, int n) {
    int chunk = (n >> 3) ^ (k & 7);
    return (uint32_t)k * 512u + (uint32_t)chunk * 16u + (uint32_t)(n & 7) * 2u;
}

// ---------------- fused prologue: zero scratch + build B_ext ----------------
__global__ __launch_bounds__(256) void k_pre(
    const float* __restrict__ Wsrc, const float* __restrict__ Wdst)
{
    int i = blockIdx.x * blockDim.x + threadIdx.x;
    int stride = gridDim.x * blockDim.x;
    for (int j = i; j < NGRAPHS * DIM; j += stride) g_hsum[j] = 0.0f;
    for (int j = i; j < NGRAPHS; j += stride) g_cnt[j] = 0.0f;
    for (int j = i; j < N_NODES; j += stride) { g_deg[j] = 0; g_cur[j] = 0; }
    for (int j = i; j < 2 * KEXT * HD; j += stride) {
        int mat  = j / (KEXT * HD);
        int r    = j % (KEXT * HD);
        int kext = r >> 8;
        int n    = r & 255;
        int k    = (kext < 2 * IN_F) ? (kext & (IN_F - 1)) : (kext - 2 * IN_F);
        const float* W = mat ? Wdst : Wsrc;
        float v = W[(size_t)k * HD + n];
        __nv_bfloat16 hi = __float2bfloat16(v);
        g_Bext[j] = (kext < 2 * IN_F) ? hi : __float2bfloat16(v - __bfloat162float(hi));
    }
}

// ---------------- bf16 mma.sync GEMM + fused dst histogram ----------------
// grid = MBLK + HBLK; blocks >= MBLK do the edge histogram (runs concurrently)
#define SM_A_BYTES 65536
#define SM_B_BYTES 16384
#define SM_TOT (SM_A_BYTES + SM_B_BYTES)

__global__ __launch_bounds__(512) void k_mgemm(
    const float* __restrict__ atom,
    const float* __restrict__ bsrc, const float* __restrict__ bdst,
    const int* __restrict__ dst)
{
    extern __shared__ char smem[];
    const int tid  = threadIdx.x;

    if (blockIdx.x >= MBLK) {          // histogram specialist blocks
        int t = (blockIdx.x - MBLK) * 512 + tid;
        for (int e = t; e < N_EDGES; e += HBLK * 512)
            atomicAdd(&g_deg[dst[e]], 1);
        return;
    }

    const uint32_t sA = smem_u32(smem);
    const uint32_t sB = sA + SM_A_BYTES;

    const int lane = tid & 31;
    const int wid  = tid >> 5;             // 0..15
    const int row0 = blockIdx.x * 128;

    // ---- A: load 128 rows x 128 fp32 once, hi/lo bf16 into smem ----
    {
        int ar = tid >> 2;                 // 0..127
        int c0 = (tid & 3) * 32;
        bool valid = (row0 + ar) < N_NODES;
        const float4* arow = (const float4*)(atom + (size_t)(row0 + ar) * IN_F + c0);
#pragma unroll
        for (int i = 0; i < 8; i++) {
            float4 v = valid ? arow[i] : make_float4(0.f, 0.f, 0.f, 0.f);
            int c = c0 + i * 4;
            __nv_bfloat162 h0 = __float22bfloat162_rn(make_float2(v.x, v.y));
            __nv_bfloat162 h1 = __float22bfloat162_rn(make_float2(v.z, v.w));
            float2 f0 = __bfloat1622float2(h0);
            float2 f1 = __bfloat1622float2(h1);
            __nv_bfloat162 l0 = __float22bfloat162_rn(make_float2(v.x - f0.x, v.y - f0.y));
            __nv_bfloat162 l1 = __float22bfloat162_rn(make_float2(v.z - f1.x, v.w - f1.y));
            uint2 hp, lp;
            hp.x = *(uint32_t*)&h0; hp.y = *(uint32_t*)&h1;
            lp.x = *(uint32_t*)&l0; lp.y = *(uint32_t*)&l1;
            *(uint2*)(smem + a_off(ar, c))       = hp;
            *(uint2*)(smem + a_off(ar, 128 + c)) = lp;
        }
    }

    const int wr = wid >> 2;               // 0..3
    const int wc = wid & 3;                // 0..3
    const int mbase = wr * 32;
    const int nbase = wc * 64;

    const int kr = tid >> 4;               // 0..31
    const int ch = tid & 15;               // 0..15
    const uint32_t bso0 = SM_A_BYTES + b_off(kr, ch * 8);
    const uint32_t bso1 = SM_A_BYTES + b_off(kr, 128 + ch * 8);

    const int a_r  = lane & 15;
    const int a_c8 = (lane >> 4) << 3;
    const int b_kr = (lane & 7) + (((lane >> 3) & 1) << 3);
    const int b_n8 = (lane >> 4) << 3;

    const int g  = lane >> 2;
    const int tg = lane & 3;

    for (int mat = 0; mat < 2; mat++) {
        const __nv_bfloat16* Bg = g_Bext + (size_t)mat * KEXT * HD;

        float acc[2][8][4];
#pragma unroll
        for (int a = 0; a < 2; a++)
#pragma unroll
            for (int b = 0; b < 8; b++)
#pragma unroll
                for (int c = 0; c < 4; c++) acc[a][b][c] = 0.0f;

        uint4 pv0 = *(const uint4*)(Bg + (size_t)kr * HD + ch * 8);
        uint4 pv1 = *(const uint4*)(Bg + (size_t)kr * HD + 128 + ch * 8);

        for (int it = 0; it < 12; it++) {
            __syncthreads();
            *(uint4*)(smem + bso0) = pv0;
            *(uint4*)(smem + bso1) = pv1;
            __syncthreads();

            if (it < 11) {
                const __nv_bfloat16* brow = Bg + (size_t)((it + 1) * 32 + kr) * HD;
                pv0 = *(const uint4*)(brow + ch * 8);
                pv1 = *(const uint4*)(brow + 128 + ch * 8);
            }

            const int kk = it * 32;
            const int term = kk >> 7;
            const int acolb = (term == 1) ? (128 + (kk & 127)) : (kk & 127);

#pragma unroll
            for (int ks = 0; ks < 32; ks += 16) {
                uint32_t af[2][4];
#pragma unroll
                for (int mi = 0; mi < 2; mi++) {
                    uint32_t addr = sA + a_off(mbase + mi * 16 + a_r, acolb + ks + a_c8);
                    asm volatile("ldmatrix.sync.aligned.m8n8.x4.shared.b16 {%0,%1,%2,%3}, [%4];"
                                 : "=r"(af[mi][0]), "=r"(af[mi][1]), "=r"(af[mi][2]), "=r"(af[mi][3])
                                 : "r"(addr));
                }
                uint32_t bf[4][4];
#pragma unroll
                for (int ni = 0; ni < 4; ni++) {
                    uint32_t addr = sB + b_off(ks + b_kr, nbase + ni * 16 + b_n8);
                    asm volatile("ldmatrix.sync.aligned.m8n8.x4.trans.shared.b16 {%0,%1,%2,%3}, [%4];"
                                 : "=r"(bf[ni][0]), "=r"(bf[ni][1]), "=r"(bf[ni][2]), "=r"(bf[ni][3])
                                 : "r"(addr));
                }
#pragma unroll
                for (int mi = 0; mi < 2; mi++)
#pragma unroll
                    for (int ni = 0; ni < 4; ni++) {
                        asm volatile(
                            "mma.sync.aligned.m16n8k16.row.col.f32.bf16.bf16.f32 "
                            "{%0,%1,%2,%3}, {%4,%5,%6,%7}, {%8,%9}, {%0,%1,%2,%3};"
                            : "+f"(acc[mi][ni*2][0]), "+f"(acc[mi][ni*2][1]),
                              "+f"(acc[mi][ni*2][2]), "+f"(acc[mi][ni*2][3])
                            : "r"(af[mi][0]), "r"(af[mi][1]), "r"(af[mi][2]), "r"(af[mi][3]),
                              "r"(bf[ni][0]), "r"(bf[ni][1]));
                        asm volatile(
                            "mma.sync.aligned.m16n8k16.row.col.f32.bf16.bf16.f32 "
                            "{%0,%1,%2,%3}, {%4,%5,%6,%7}, {%8,%9}, {%0,%1,%2,%3};"
                            : "+f"(acc[mi][ni*2+1][0]), "+f"(acc[mi][ni*2+1][1]),
                              "+f"(acc[mi][ni*2+1][2]), "+f"(acc[mi][ni*2+1][3])
                            : "r"(af[mi][0]), "r"(af[mi][1]), "r"(af[mi][2]), "r"(af[mi][3]),
                              "r"(bf[ni][2]), "r"(bf[ni][3]));
                    }
            }
        }

        const float* bias = mat ? bdst : bsrc;
        float* outp       = mat ? g_fd : g_fs;
#pragma unroll
        for (int mi = 0; mi < 2; mi++) {
#pragma unroll
            for (int n8 = 0; n8 < 8; n8++) {
                int colg = nbase + n8 * 8 + tg * 2;
                float b0 = __ldg(bias + colg);
                float b1 = __ldg(bias + colg + 1);
                int r1 = row0 + mbase + mi * 16 + g;
                int r2 = r1 + 8;
                if (r1 < N_NODES) {
                    float2 v = make_float2(acc[mi][n8][0] + b0, acc[mi][n8][1] + b1);
                    *(float2*)(outp + (size_t)r1 * HD + colg) = v;
                }
                if (r2 < N_NODES) {
                    float2 v = make_float2(acc[mi][n8][2] + b0, acc[mi][n8][3] + b1);
                    *(float2*)(outp + (size_t)r2 * HD + colg) = v;
                }
            }
        }
    }
}

// ---------------- scans ----------------
__global__ __launch_bounds__(256) void k_scan1() {
    __shared__ int sh[256];
    int i = blockIdx.x * 256 + threadIdx.x;
    int v = (i < N_NODES) ? g_deg[i] : 0;
    sh[threadIdx.x] = v;
    __syncthreads();
    for (int d = 1; d < 256; d <<= 1) {
        int t = (threadIdx.x >= d) ? sh[threadIdx.x - d] : 0;
        __syncthreads();
        sh[threadIdx.x] += t;
        __syncthreads();
    }
    if (threadIdx.x == 255) g_blksum[blockIdx.x] = sh[255];
}

__global__ __launch_bounds__(256) void k_scanB() {
    __shared__ int sh[256];
    __shared__ int wsum[8];
    __shared__ int base_s;
    int b = blockIdx.x;
    int t = threadIdx.x;

    int v = (t < b) ? g_blksum[t] : 0;
#pragma unroll
    for (int d = 16; d; d >>= 1) v += __shfl_down_sync(0xFFFFFFFFu, v, d);
    if ((t & 31) == 0) wsum[t >> 5] = v;
    __syncthreads();
    if (t == 0) {
        int s = 0;
#pragma unroll
        for (int j = 0; j < 8; j++) s += wsum[j];
        base_s = s;
    }
    __syncthreads();

    int i = b * 256 + t;
    int dv = (i < N_NODES) ? g_deg[i] : 0;
    sh[t] = dv;
    __syncthreads();
    for (int d = 1; d < 256; d <<= 1) {
        int x = (t >= d) ? sh[t - d] : 0;
        __syncthreads();
        sh[t] += x;
        __syncthreads();
    }
    if (i < N_NODES) g_off[i] = base_s + sh[t] - dv;
}

__global__ __launch_bounds__(256) void k_fill(
    const int* __restrict__ dst, const int* __restrict__ src)
{
    int e = blockIdx.x * blockDim.x + threadIdx.x;
    if (e >= N_EDGES) return;
    int d = dst[e];
    int pos = atomicAdd(&g_cur[d], 1);
    g_epack[g_off[d] + pos] = make_int2(e, src[e]);
}

// ---------------- fused per-node online-softmax aggregation (R8 structure) ----------------
__global__ __launch_bounds__(256) void k_agg(
    const float* __restrict__ attn,
    const int* __restrict__ gid, float* __restrict__ x1)
{
    int warp = (blockIdx.x * blockDim.x + threadIdx.x) >> 5;
    if (warp >= N_NODES) return;
    int n = warp;
    int lane = threadIdx.x & 31;
    int base = lane * 8;
    int h = lane >> 3;

    float4 fd0 = *(const float4*)(g_fd + (size_t)n * HD + base);
    float4 fd1 = *(const float4*)(g_fd + (size_t)n * HD + base + 4);
    float4 aw0 = __ldg((const float4*)(attn + base));
    float4 aw1 = __ldg((const float4*)(attn + base + 4));

    int deg = g_deg[n];
    int off = g_off[n];

    float m = __int_as_float(0xff800000);
    float den = 0.0f;
    float acc[8];
#pragma unroll
    for (int j = 0; j < 8; j++) acc[j] = 0.0f;

    for (int i = 0; i < deg; i++) {
        int2 es = g_epack[off + i];
        const float4* pfs = (const float4*)(g_fs + (size_t)es.y * HD + base);
        float4 a0 = pfs[0], a1 = pfs[1];

        float e_val;
        e_val  = lrelu(a0.x + fd0.x) * aw0.x;
        e_val += lrelu(a0.y + fd0.y) * aw0.y;
        e_val += lrelu(a0.z + fd0.z) * aw0.z;
        e_val += lrelu(a0.w + fd0.w) * aw0.w;
        e_val += lrelu(a1.x + fd1.x) * aw1.x;
        e_val += lrelu(a1.y + fd1.y) * aw1.y;
        e_val += lrelu(a1.z + fd1.z) * aw1.z;
        e_val += lrelu(a1.w + fd1.w) * aw1.w;
        e_val += __shfl_xor_sync(0xFFFFFFFFu, e_val, 1);
        e_val += __shfl_xor_sync(0xFFFFFFFFu, e_val, 2);
        e_val += __shfl_xor_sync(0xFFFFFFFFu, e_val, 4);

        if ((lane & 7) == 0)
            g_e[(size_t)es.x * HEADS + h] = e_val;

        float m_new = fmaxf(m, e_val);
        float scale = __expf(m - m_new);
        float ex    = __expf(e_val - m_new);
        den = den * scale + ex;
        acc[0] = acc[0] * scale + ex * a0.x;
        acc[1] = acc[1] * scale + ex * a0.y;
        acc[2] = acc[2] * scale + ex * a0.z;
        acc[3] = acc[3] * scale + ex * a0.w;
        acc[4] = acc[4] * scale + ex * a1.x;
        acc[5] = acc[5] * scale + ex * a1.y;
        acc[6] = acc[6] * scale + ex * a1.z;
        acc[7] = acc[7] * scale + ex * a1.w;
        m = m_new;
    }

    if (deg > 0 && (lane & 7) == 0) {
        g_m  [n * HEADS + h] = m;
        g_den[n * HEADS + h] = den;
    }

    float inv = (den > 0.0f) ? (1.0f / den) : 0.0f;
    float r[8];
#pragma unroll
    for (int j = 0; j < 8; j++) {
        r[j] = acc[j] * inv;
        r[j] += __shfl_xor_sync(0xFFFFFFFFu, r[j], 8);
        r[j] += __shfl_xor_sync(0xFFFFFFFFu, r[j], 16);
        r[j] *= 0.25f;
    }

    int g = gid[n];
    if (lane < 8) {
        float4 v0 = make_float4(r[0], r[1], r[2], r[3]);
        float4 v1 = make_float4(r[4], r[5], r[6], r[7]);
        float* xp = x1 + (size_t)n * DIM + lane * 8;
        *(float4*)(xp)     = v0;
        *(float4*)(xp + 4) = v1;
        atomicAdd((float4*)(g_hsum + (size_t)g * DIM + lane * 8),     v0);
        atomicAdd((float4*)(g_hsum + (size_t)g * DIM + lane * 8 + 4), v1);
    }
    if (lane == 0) atomicAdd(&g_cnt[g], 1.0f);
}

// ---------------- score ----------------
__global__ __launch_bounds__(256) void k_score(
    const int* __restrict__ dst, float* __restrict__ score)
{
    int idx = blockIdx.x * blockDim.x + threadIdx.x;
    if (idx >= N_EDGES * HEADS) return;
    int e = idx >> 2, h = idx & 3;
    int d = dst[e];
    float alpha = __expf(g_e[idx] - g_m[d * HEADS + h]) / g_den[d * HEADS + h];
    score[idx] = alpha;
}

// ---------------- graph mean finalize ----------------
__global__ __launch_bounds__(256) void k_final(float* __restrict__ hout)
{
    int idx = blockIdx.x * blockDim.x + threadIdx.x;
    if (idx >= NGRAPHS * DIM) return;
    int g = idx >> 6;
    hout[idx] = g_hsum[idx] / fmaxf(g_cnt[g], 1.0f);
}

// ---------------- launcher ----------------
extern "C" void kernel_launch(void* const* d_in, const int* in_sizes, int n_in,
                              void* d_out, int out_size)
{
    (void)in_sizes; (void)n_in; (void)out_size;

    const float* atom = (const float*)d_in[0];
    const float* Wsrc = (const float*)d_in[1];
    const float* bsrc = (const float*)d_in[2];
    const float* Wdst = (const float*)d_in[3];
    const float* bdst = (const float*)d_in[4];
    const float* attn = (const float*)d_in[5];
    const int*   src  = (const int*)d_in[6];
    const int*   dst  = (const int*)d_in[7];
    const int*   gid  = (const int*)d_in[8];

    float* out   = (float*)d_out;
    float* x1    = out;
    float* hout  = out + (size_t)N_NODES * DIM;
    float* score = hout + (size_t)NGRAPHS * DIM;

    cudaFuncSetAttribute(k_mgemm, cudaFuncAttributeMaxDynamicSharedMemorySize, SM_TOT);

    k_pre<<<512, 256>>>(Wsrc, Wdst);                      // zero + B_ext

    k_mgemm<<<MBLK + HBLK, 512, SM_TOT>>>(atom, bsrc, bdst, dst);  // gemm + hist

    k_scan1<<<SCAN_NB, 256>>>();
    k_scanB<<<SCAN_NB, 256>>>();

    int eblocks = (N_EDGES + 255) / 256;
    k_fill<<<eblocks, 256>>>(dst, src);

    k_agg<<<(N_NODES * 32 + 255) / 256, 256>>>(attn, gid, x1);

    k_score<<<(N_EDGES * HEADS + 255) / 256, 256>>>(dst, score);

    k_final<<<(NGRAPHS * DIM + 255) / 256, 256>>>(hout);
}

// round 12
// speedup vs baseline: 1.1061x; 1.0098x over previous
#include <cuda_runtime.h>
#include <cuda_bf16.h>
#include <cstdint>

// ---------------- problem constants ----------------
#define N_NODES  50000
#define N_EDGES  400000
#define IN_F     128
#define HEADS    4
#define DIM      64
#define HD       256           // HEADS*DIM
#define NGRAPHS  2000
#define NEG_SLOPE 0.2f
#define SCAN_NB  196           // ceil(50000/256)
#define KEXT     384           // 3 * IN_F (bf16 split terms)
#define MBLK     391           // gemm blocks

// ---------------- device scratch ----------------
__device__ float g_fs[(size_t)N_NODES * HD];
__device__ float g_fd[(size_t)N_NODES * HD];
__device__ float g_e [(size_t)N_EDGES * HEADS];
__device__ float g_hsum[NGRAPHS * DIM];
__device__ float g_cnt [NGRAPHS];
__device__ int   g_deg[N_NODES];
__device__ int   g_cur[N_NODES];
__device__ int   g_off[N_NODES];
__device__ int2  g_epack[N_EDGES];        // {edge_id, src}
__device__ int   g_blksum[SCAN_NB];
__device__ __align__(16) __nv_bfloat16 g_Bext[2 * KEXT * HD];

__device__ __forceinline__ float lrelu(float x) {
    return x > 0.0f ? x : NEG_SLOPE * x;
}

__device__ __forceinline__ uint32_t smem_u32(const void* p) {
    uint32_t a;
    asm("{ .reg .u64 t; cvta.to.shared.u64 t, %1; cvt.u32.u64 %0, t; }" : "=r"(a) : "l"(p));
    return a;
}

// A smem: 128 rows x 256 bf16 cols (hi | lo), 512 B/row
__device__ __forceinline__ uint32_t a_off(int r, int c) {
    int chunk = (c >> 3) ^ (r & 7);
    return (uint32_t)r * 512u + (uint32_t)chunk * 16u + (uint32_t)(c & 7) * 2u;
}
// B smem: 32 k-rows x 256 bf16 cols, 512 B/row
__device__ __forceinline__ uint32_t b_off(int k, int n) {
    int chunk = (n >> 3) ^ (k & 7);
    return (uint32_t)k * 512u + (uint32_t)chunk * 16u + (uint32_t)(n & 7) * 2u;
}

// ---------------- fused prologue: zero scratch + build B_ext ----------------
__global__ __launch_bounds__(256) void k_pre(
    const float* __restrict__ Wsrc, const float* __restrict__ Wdst)
{
    int i = blockIdx.x * blockDim.x + threadIdx.x;
    int stride = gridDim.x * blockDim.x;
    for (int j = i; j < NGRAPHS * DIM; j += stride) g_hsum[j] = 0.0f;
    for (int j = i; j < NGRAPHS; j += stride) g_cnt[j] = 0.0f;
    for (int j = i; j < N_NODES; j += stride) { g_deg[j] = 0; g_cur[j] = 0; }
    for (int j = i; j < 2 * KEXT * HD; j += stride) {
        int mat  = j / (KEXT * HD);
        int r    = j % (KEXT * HD);
        int kext = r >> 8;
        int n    = r & 255;
        int k    = (kext < 2 * IN_F) ? (kext & (IN_F - 1)) : (kext - 2 * IN_F);
        const float* W = mat ? Wdst : Wsrc;
        float v = W[(size_t)k * HD + n];
        __nv_bfloat16 hi = __float2bfloat16(v);
        g_Bext[j] = (kext < 2 * IN_F) ? hi : __float2bfloat16(v - __bfloat162float(hi));
    }
}

__global__ __launch_bounds__(256) void k_hist(const int* __restrict__ dst) {
    int e = blockIdx.x * blockDim.x + threadIdx.x;
    if (e < N_EDGES) atomicAdd(&g_deg[dst[e]], 1);
}

// ---------------- bf16 mma.sync GEMM ----------------
#define SM_A_BYTES 65536
#define SM_B_BYTES 16384
#define SM_TOT (SM_A_BYTES + SM_B_BYTES)

__global__ __launch_bounds__(512) void k_mgemm(
    const float* __restrict__ atom,
    const float* __restrict__ bsrc, const float* __restrict__ bdst)
{
    extern __shared__ char smem[];
    const int tid  = threadIdx.x;
    const uint32_t sA = smem_u32(smem);
    const uint32_t sB = sA + SM_A_BYTES;

    const int lane = tid & 31;
    const int wid  = tid >> 5;             // 0..15
    const int row0 = blockIdx.x * 128;

    // ---- A: load 128 rows x 128 fp32 once, hi/lo bf16 into smem ----
    {
        int ar = tid >> 2;                 // 0..127
        int c0 = (tid & 3) * 32;
        bool valid = (row0 + ar) < N_NODES;
        const float4* arow = (const float4*)(atom + (size_t)(row0 + ar) * IN_F + c0);
#pragma unroll
        for (int i = 0; i < 8; i++) {
            float4 v = valid ? arow[i] : make_float4(0.f, 0.f, 0.f, 0.f);
            int c = c0 + i * 4;
            __nv_bfloat162 h0 = __float22bfloat162_rn(make_float2(v.x, v.y));
            __nv_bfloat162 h1 = __float22bfloat162_rn(make_float2(v.z, v.w));
            float2 f0 = __bfloat1622float2(h0);
            float2 f1 = __bfloat1622float2(h1);
            __nv_bfloat162 l0 = __float22bfloat162_rn(make_float2(v.x - f0.x, v.y - f0.y));
            __nv_bfloat162 l1 = __float22bfloat162_rn(make_float2(v.z - f1.x, v.w - f1.y));
            uint2 hp, lp;
            hp.x = *(uint32_t*)&h0; hp.y = *(uint32_t*)&h1;
            lp.x = *(uint32_t*)&l0; lp.y = *(uint32_t*)&l1;
            *(uint2*)(smem + a_off(ar, c))       = hp;
            *(uint2*)(smem + a_off(ar, 128 + c)) = lp;
        }
    }

    const int wr = wid >> 2;               // 0..3
    const int wc = wid & 3;                // 0..3
    const int mbase = wr * 32;
    const int nbase = wc * 64;

    const int kr = tid >> 4;               // 0..31
    const int ch = tid & 15;               // 0..15
    const uint32_t bso0 = SM_A_BYTES + b_off(kr, ch * 8);
    const uint32_t bso1 = SM_A_BYTES + b_off(kr, 128 + ch * 8);

    const int a_r  = lane & 15;
    const int a_c8 = (lane >> 4) << 3;
    const int b_kr = (lane & 7) + (((lane >> 3) & 1) << 3);
    const int b_n8 = (lane >> 4) << 3;

    const int g  = lane >> 2;
    const int tg = lane & 3;

    for (int mat = 0; mat < 2; mat++) {
        const __nv_bfloat16* Bg = g_Bext + (size_t)mat * KEXT * HD;

        float acc[2][8][4];
#pragma unroll
        for (int a = 0; a < 2; a++)
#pragma unroll
            for (int b = 0; b < 8; b++)
#pragma unroll
                for (int c = 0; c < 4; c++) acc[a][b][c] = 0.0f;

        uint4 pv0 = *(const uint4*)(Bg + (size_t)kr * HD + ch * 8);
        uint4 pv1 = *(const uint4*)(Bg + (size_t)kr * HD + 128 + ch * 8);

        for (int it = 0; it < 12; it++) {
            __syncthreads();
            *(uint4*)(smem + bso0) = pv0;
            *(uint4*)(smem + bso1) = pv1;
            __syncthreads();

            if (it < 11) {
                const __nv_bfloat16* brow = Bg + (size_t)((it + 1) * 32 + kr) * HD;
                pv0 = *(const uint4*)(brow + ch * 8);
                pv1 = *(const uint4*)(brow + 128 + ch * 8);
            }

            const int kk = it * 32;
            const int term = kk >> 7;
            const int acolb = (term == 1) ? (128 + (kk & 127)) : (kk & 127);

#pragma unroll
            for (int ks = 0; ks < 32; ks += 16) {
                uint32_t af[2][4];
#pragma unroll
                for (int mi = 0; mi < 2; mi++) {
                    uint32_t addr = sA + a_off(mbase + mi * 16 + a_r, acolb + ks + a_c8);
                    asm volatile("ldmatrix.sync.aligned.m8n8.x4.shared.b16 {%0,%1,%2,%3}, [%4];"
                                 : "=r"(af[mi][0]), "=r"(af[mi][1]), "=r"(af[mi][2]), "=r"(af[mi][3])
                                 : "r"(addr));
                }
                uint32_t bf[4][4];
#pragma unroll
                for (int ni = 0; ni < 4; ni++) {
                    uint32_t addr = sB + b_off(ks + b_kr, nbase + ni * 16 + b_n8);
                    asm volatile("ldmatrix.sync.aligned.m8n8.x4.trans.shared.b16 {%0,%1,%2,%3}, [%4];"
                                 : "=r"(bf[ni][0]), "=r"(bf[ni][1]), "=r"(bf[ni][2]), "=r"(bf[ni][3])
                                 : "r"(addr));
                }
#pragma unroll
                for (int mi = 0; mi < 2; mi++)
#pragma unroll
                    for (int ni = 0; ni < 4; ni++) {
                        asm volatile(
                            "mma.sync.aligned.m16n8k16.row.col.f32.bf16.bf16.f32 "
                            "{%0,%1,%2,%3}, {%4,%5,%6,%7}, {%8,%9}, {%0,%1,%2,%3};"
                            : "+f"(acc[mi][ni*2][0]), "+f"(acc[mi][ni*2][1]),
                              "+f"(acc[mi][ni*2][2]), "+f"(acc[mi][ni*2][3])
                            : "r"(af[mi][0]), "r"(af[mi][1]), "r"(af[mi][2]), "r"(af[mi][3]),
                              "r"(bf[ni][0]), "r"(bf[ni][1]));
                        asm volatile(
                            "mma.sync.aligned.m16n8k16.row.col.f32.bf16.bf16.f32 "
                            "{%0,%1,%2,%3}, {%4,%5,%6,%7}, {%8,%9}, {%0,%1,%2,%3};"
                            : "+f"(acc[mi][ni*2+1][0]), "+f"(acc[mi][ni*2+1][1]),
                              "+f"(acc[mi][ni*2+1][2]), "+f"(acc[mi][ni*2+1][3])
                            : "r"(af[mi][0]), "r"(af[mi][1]), "r"(af[mi][2]), "r"(af[mi][3]),
                              "r"(bf[ni][2]), "r"(bf[ni][3]));
                    }
            }
        }

        const float* bias = mat ? bdst : bsrc;
        float* outp       = mat ? g_fd : g_fs;
#pragma unroll
        for (int mi = 0; mi < 2; mi++) {
#pragma unroll
            for (int n8 = 0; n8 < 8; n8++) {
                int colg = nbase + n8 * 8 + tg * 2;
                float b0 = __ldg(bias + colg);
                float b1 = __ldg(bias + colg + 1);
                int r1 = row0 + mbase + mi * 16 + g;
                int r2 = r1 + 8;
                if (r1 < N_NODES) {
                    float2 v = make_float2(acc[mi][n8][0] + b0, acc[mi][n8][1] + b1);
                    *(float2*)(outp + (size_t)r1 * HD + colg) = v;
                }
                if (r2 < N_NODES) {
                    float2 v = make_float2(acc[mi][n8][2] + b0, acc[mi][n8][3] + b1);
                    *(float2*)(outp + (size_t)r2 * HD + colg) = v;
                }
            }
        }
    }
}

// ---------------- scans ----------------
__global__ __launch_bounds__(256) void k_scan1() {
    __shared__ int sh[256];
    int i = blockIdx.x * 256 + threadIdx.x;
    int v = (i < N_NODES) ? g_deg[i] : 0;
    sh[threadIdx.x] = v;
    __syncthreads();
    for (int d = 1; d < 256; d <<= 1) {
        int t = (threadIdx.x >= d) ? sh[threadIdx.x - d] : 0;
        __syncthreads();
        sh[threadIdx.x] += t;
        __syncthreads();
    }
    if (threadIdx.x == 255) g_blksum[blockIdx.x] = sh[255];
}

__global__ __launch_bounds__(256) void k_scanB() {
    __shared__ int sh[256];
    __shared__ int wsum[8];
    __shared__ int base_s;
    int b = blockIdx.x;
    int t = threadIdx.x;

    int v = (t < b) ? g_blksum[t] : 0;
#pragma unroll
    for (int d = 16; d; d >>= 1) v += __shfl_down_sync(0xFFFFFFFFu, v, d);
    if ((t & 31) == 0) wsum[t >> 5] = v;
    __syncthreads();
    if (t == 0) {
        int s = 0;
#pragma unroll
        for (int j = 0; j < 8; j++) s += wsum[j];
        base_s = s;
    }
    __syncthreads();

    int i = b * 256 + t;
    int dv = (i < N_NODES) ? g_deg[i] : 0;
    sh[t] = dv;
    __syncthreads();
    for (int d = 1; d < 256; d <<= 1) {
        int x = (t >= d) ? sh[t - d] : 0;
        __syncthreads();
        sh[t] += x;
        __syncthreads();
    }
    if (i < N_NODES) g_off[i] = base_s + sh[t] - dv;
}

__global__ __launch_bounds__(256) void k_fill(
    const int* __restrict__ dst, const int* __restrict__ src)
{
    int e = blockIdx.x * blockDim.x + threadIdx.x;
    if (e >= N_EDGES) return;
    int d = dst[e];
    int pos = atomicAdd(&g_cur[d], 1);
    g_epack[g_off[d] + pos] = make_int2(e, src[e]);
}

// ---------------- fused per-node aggregation + score ----------------
__global__ __launch_bounds__(256) void k_agg(
    const float* __restrict__ attn,
    const int* __restrict__ gid, float* __restrict__ x1,
    float* __restrict__ score)
{
    int warp = (blockIdx.x * blockDim.x + threadIdx.x) >> 5;
    if (warp >= N_NODES) return;
    int n = warp;
    int lane = threadIdx.x & 31;
    int base = lane * 8;
    int h = lane >> 3;

    float4 fd0 = *(const float4*)(g_fd + (size_t)n * HD + base);
    float4 fd1 = *(const float4*)(g_fd + (size_t)n * HD + base + 4);
    float4 aw0 = __ldg((const float4*)(attn + base));
    float4 aw1 = __ldg((const float4*)(attn + base + 4));

    int deg = g_deg[n];
    int off = g_off[n];

    float m = __int_as_float(0xff800000);
    float den = 0.0f;
    float acc[8];
#pragma unroll
    for (int j = 0; j < 8; j++) acc[j] = 0.0f;

    for (int i = 0; i < deg; i++) {
        int2 es = g_epack[off + i];
        const float4* pfs = (const float4*)(g_fs + (size_t)es.y * HD + base);
        float4 a0 = pfs[0], a1 = pfs[1];

        float e_val;
        e_val  = lrelu(a0.x + fd0.x) * aw0.x;
        e_val += lrelu(a0.y + fd0.y) * aw0.y;
        e_val += lrelu(a0.z + fd0.z) * aw0.z;
        e_val += lrelu(a0.w + fd0.w) * aw0.w;
        e_val += lrelu(a1.x + fd1.x) * aw1.x;
        e_val += lrelu(a1.y + fd1.y) * aw1.y;
        e_val += lrelu(a1.z + fd1.z) * aw1.z;
        e_val += lrelu(a1.w + fd1.w) * aw1.w;
        e_val += __shfl_xor_sync(0xFFFFFFFFu, e_val, 1);
        e_val += __shfl_xor_sync(0xFFFFFFFFu, e_val, 2);
        e_val += __shfl_xor_sync(0xFFFFFFFFu, e_val, 4);

        if ((lane & 7) == 0)
            g_e[(size_t)es.x * HEADS + h] = e_val;

        float m_new = fmaxf(m, e_val);
        float scale = __expf(m - m_new);
        float ex    = __expf(e_val - m_new);
        den = den * scale + ex;
        acc[0] = acc[0] * scale + ex * a0.x;
        acc[1] = acc[1] * scale + ex * a0.y;
        acc[2] = acc[2] * scale + ex * a0.z;
        acc[3] = acc[3] * scale + ex * a0.w;
        acc[4] = acc[4] * scale + ex * a1.x;
        acc[5] = acc[5] * scale + ex * a1.y;
        acc[6] = acc[6] * scale + ex * a1.z;
        acc[7] = acc[7] * scale + ex * a1.w;
        m = m_new;
    }

    // ---- node output: rst/den, head mean, graph pool ----
    float inv = (den > 0.0f) ? (1.0f / den) : 0.0f;
    float r[8];
#pragma unroll
    for (int j = 0; j < 8; j++) {
        r[j] = acc[j] * inv;
        r[j] += __shfl_xor_sync(0xFFFFFFFFu, r[j], 8);
        r[j] += __shfl_xor_sync(0xFFFFFFFFu, r[j], 16);
        r[j] *= 0.25f;
    }

    int g = gid[n];
    if (lane < 8) {
        float4 v0 = make_float4(r[0], r[1], r[2], r[3]);
        float4 v1 = make_float4(r[4], r[5], r[6], r[7]);
        float* xp = x1 + (size_t)n * DIM + lane * 8;
        *(float4*)(xp)     = v0;
        *(float4*)(xp + 4) = v1;
        atomicAdd((float4*)(g_hsum + (size_t)g * DIM + lane * 8),     v0);
        atomicAdd((float4*)(g_hsum + (size_t)g * DIM + lane * 8 + 4), v1);
    }
    if (lane == 0) atomicAdd(&g_cnt[g], 1.0f);

    // ---- fused score: alpha = exp(e - m)/den for this node's edges ----
    // head hh's (m, den) live in lane hh*8 (group-uniform within each 8-lane head group)
    if (deg > 0) {
        __threadfence_block();             // make g_e writes visible across lanes
        __syncwarp();
        int hh = lane & 3;
        float m_h = __shfl_sync(0xFFFFFFFFu, m,   hh << 3);
        float d_h = __shfl_sync(0xFFFFFFFFu, den, hh << 3);
        float dinv = 1.0f / d_h;
        for (int i0 = 0; i0 < deg; i0 += 8) {
            int ei = i0 + (lane >> 2);
            if (ei < deg) {
                int eid = g_epack[off + ei].x;
                float ev = g_e[(size_t)eid * HEADS + hh];
                score[(size_t)eid * HEADS + hh] = __expf(ev - m_h) * dinv;
            }
        }
    }
}

// ---------------- graph mean finalize ----------------
__global__ __launch_bounds__(256) void k_final(float* __restrict__ hout)
{
    int idx = blockIdx.x * blockDim.x + threadIdx.x;
    if (idx >= NGRAPHS * DIM) return;
    int g = idx >> 6;
    hout[idx] = g_hsum[idx] / fmaxf(g_cnt[g], 1.0f);
}

// ---------------- launcher ----------------
extern "C" void kernel_launch(void* const* d_in, const int* in_sizes, int n_in,
                              void* d_out, int out_size)
{
    (void)in_sizes; (void)n_in; (void)out_size;

    const float* atom = (const float*)d_in[0];
    const float* Wsrc = (const float*)d_in[1];
    const float* bsrc = (const float*)d_in[2];
    const float* Wdst = (const float*)d_in[3];
    const float* bdst = (const float*)d_in[4];
    const float* attn = (const float*)d_in[5];
    const int*   src  = (const int*)d_in[6];
    const int*   dst  = (const int*)d_in[7];
    const int*   gid  = (const int*)d_in[8];

    float* out   = (float*)d_out;
    float* x1    = out;
    float* hout  = out + (size_t)N_NODES * DIM;
    float* score = hout + (size_t)NGRAPHS * DIM;

    static bool inited = false;
    static cudaStream_t sB;
    static cudaEvent_t evF, evJ;
    if (!inited) {
        cudaStreamCreateWithFlags(&sB, cudaStreamNonBlocking);
        cudaEventCreateWithFlags(&evF, cudaEventDisableTiming);
        cudaEventCreateWithFlags(&evJ, cudaEventDisableTiming);
        inited = true;
    }

    cudaFuncSetAttribute(k_mgemm, cudaFuncAttributeMaxDynamicSharedMemorySize, SM_TOT);

    // prologue on main stream (zeros g_deg needed by hist, builds B_ext for gemm)
    k_pre<<<512, 256>>>(Wsrc, Wdst);

    // fork: CSR chain on sB, GEMM on main stream
    cudaEventRecord(evF, 0);
    cudaStreamWaitEvent(sB, evF, 0);

    int eblocks = (N_EDGES + 255) / 256;
    k_hist <<<eblocks, 256, 0, sB>>>(dst);
    k_scan1<<<SCAN_NB, 256, 0, sB>>>();
    k_scanB<<<SCAN_NB, 256, 0, sB>>>();
    k_fill <<<eblocks, 256, 0, sB>>>(dst, src);
    cudaEventRecord(evJ, sB);

    k_mgemm<<<MBLK, 512, SM_TOT>>>(atom, bsrc, bdst);

    // join: agg needs both GEMM output and CSR
    cudaStreamWaitEvent(0, evJ, 0);

    k_agg<<<(N_NODES * 32 + 255) / 256, 256>>>(attn, gid, x1, score);

    k_final<<<(NGRAPHS * DIM + 255) / 256, 256>>>(hout);
}

// round 13
// speedup vs baseline: 1.2057x; 1.0901x over previous
#include <cuda_runtime.h>
#include <cuda_bf16.h>
#include <cstdint>

// ---------------- problem constants ----------------
#define N_NODES  50000
#define N_EDGES  400000
#define IN_F     128
#define HEADS    4
#define DIM      64
#define HD       256           // HEADS*DIM
#define NGRAPHS  2000
#define NEG_SLOPE 0.2f
#define SCAN_NB  196           // ceil(50000/256)
#define KEXT     384           // 3 * IN_F (bf16 split terms)
#define MBLK     391           // gemm blocks

// ---------------- device scratch ----------------
__device__ float g_fs[(size_t)N_NODES * HD];
__device__ float g_fd[(size_t)N_NODES * HD];
__device__ float g_e [(size_t)N_EDGES * HEADS];
__device__ float g_hsum[NGRAPHS * DIM];
__device__ float g_cnt [NGRAPHS];
__device__ int   g_deg[N_NODES];
__device__ int   g_cur[N_NODES];
__device__ int   g_off[N_NODES];
__device__ int2  g_epack[N_EDGES];        // {edge_id, src}
__device__ int   g_blksum[SCAN_NB];
__device__ __align__(16) __nv_bfloat16 g_Bext[2 * KEXT * HD];

__device__ __forceinline__ float lrelu(float x) {
    return x > 0.0f ? x : NEG_SLOPE * x;
}

__device__ __forceinline__ uint32_t smem_u32(const void* p) {
    uint32_t a;
    asm("{ .reg .u64 t; cvta.to.shared.u64 t, %1; cvt.u32.u64 %0, t; }" : "=r"(a) : "l"(p));
    return a;
}

// A smem: 128 rows x 256 bf16 cols (hi | lo), 512 B/row
__device__ __forceinline__ uint32_t a_off(int r, int c) {
    int chunk = (c >> 3) ^ (r & 7);
    return (uint32_t)r * 512u + (uint32_t)chunk * 16u + (uint32_t)(c & 7) * 2u;
}
// B smem: 32 k-rows x 256 bf16 cols, 512 B/row
__device__ __forceinline__ uint32_t b_off(int k, int n) {
    int chunk = (n >> 3) ^ (k & 7);
    return (uint32_t)k * 512u + (uint32_t)chunk * 16u + (uint32_t)(n & 7) * 2u;
}

// ---------------- fused prologue: zero scratch + build B_ext ----------------
__global__ __launch_bounds__(256) void k_pre(
    const float* __restrict__ Wsrc, const float* __restrict__ Wdst)
{
    int i = blockIdx.x * blockDim.x + threadIdx.x;
    int stride = gridDim.x * blockDim.x;
    for (int j = i; j < NGRAPHS * DIM; j += stride) g_hsum[j] = 0.0f;
    for (int j = i; j < NGRAPHS; j += stride) g_cnt[j] = 0.0f;
    for (int j = i; j < N_NODES; j += stride) { g_deg[j] = 0; g_cur[j] = 0; }
    for (int j = i; j < 2 * KEXT * HD; j += stride) {
        int mat  = j / (KEXT * HD);
        int r    = j % (KEXT * HD);
        int kext = r >> 8;
        int n    = r & 255;
        int k    = (kext < 2 * IN_F) ? (kext & (IN_F - 1)) : (kext - 2 * IN_F);
        const float* W = mat ? Wdst : Wsrc;
        float v = W[(size_t)k * HD + n];
        __nv_bfloat16 hi = __float2bfloat16(v);
        g_Bext[j] = (kext < 2 * IN_F) ? hi : __float2bfloat16(v - __bfloat162float(hi));
    }
}

__global__ __launch_bounds__(256) void k_hist(const int* __restrict__ dst) {
    int e = blockIdx.x * blockDim.x + threadIdx.x;
    if (e < N_EDGES) atomicAdd(&g_deg[dst[e]], 1);
}

// ---------------- bf16 mma.sync GEMM ----------------
#define SM_A_BYTES 65536
#define SM_B_BYTES 16384
#define SM_TOT (SM_A_BYTES + SM_B_BYTES)

__global__ __launch_bounds__(512) void k_mgemm(
    const float* __restrict__ atom,
    const float* __restrict__ bsrc, const float* __restrict__ bdst)
{
    extern __shared__ char smem[];
    const int tid  = threadIdx.x;
    const uint32_t sA = smem_u32(smem);
    const uint32_t sB = sA + SM_A_BYTES;

    const int lane = tid & 31;
    const int wid  = tid >> 5;             // 0..15
    const int row0 = blockIdx.x * 128;

    // ---- A: load 128 rows x 128 fp32 once, hi/lo bf16 into smem ----
    {
        int ar = tid >> 2;                 // 0..127
        int c0 = (tid & 3) * 32;
        bool valid = (row0 + ar) < N_NODES;
        const float4* arow = (const float4*)(atom + (size_t)(row0 + ar) * IN_F + c0);
#pragma unroll
        for (int i = 0; i < 8; i++) {
            float4 v = valid ? arow[i] : make_float4(0.f, 0.f, 0.f, 0.f);
            int c = c0 + i * 4;
            __nv_bfloat162 h0 = __float22bfloat162_rn(make_float2(v.x, v.y));
            __nv_bfloat162 h1 = __float22bfloat162_rn(make_float2(v.z, v.w));
            float2 f0 = __bfloat1622float2(h0);
            float2 f1 = __bfloat1622float2(h1);
            __nv_bfloat162 l0 = __float22bfloat162_rn(make_float2(v.x - f0.x, v.y - f0.y));
            __nv_bfloat162 l1 = __float22bfloat162_rn(make_float2(v.z - f1.x, v.w - f1.y));
            uint2 hp, lp;
            hp.x = *(uint32_t*)&h0; hp.y = *(uint32_t*)&h1;
            lp.x = *(uint32_t*)&l0; lp.y = *(uint32_t*)&l1;
            *(uint2*)(smem + a_off(ar, c))       = hp;
            *(uint2*)(smem + a_off(ar, 128 + c)) = lp;
        }
    }

    const int wr = wid >> 2;               // 0..3
    const int wc = wid & 3;                // 0..3
    const int mbase = wr * 32;
    const int nbase = wc * 64;

    const int kr = tid >> 4;               // 0..31
    const int ch = tid & 15;               // 0..15
    const uint32_t bso0 = SM_A_BYTES + b_off(kr, ch * 8);
    const uint32_t bso1 = SM_A_BYTES + b_off(kr, 128 + ch * 8);

    const int a_r  = lane & 15;
    const int a_c8 = (lane >> 4) << 3;
    const int b_kr = (lane & 7) + (((lane >> 3) & 1) << 3);
    const int b_n8 = (lane >> 4) << 3;

    const int g  = lane >> 2;
    const int tg = lane & 3;

    for (int mat = 0; mat < 2; mat++) {
        const __nv_bfloat16* Bg = g_Bext + (size_t)mat * KEXT * HD;

        float acc[2][8][4];
#pragma unroll
        for (int a = 0; a < 2; a++)
#pragma unroll
            for (int b = 0; b < 8; b++)
#pragma unroll
                for (int c = 0; c < 4; c++) acc[a][b][c] = 0.0f;

        uint4 pv0 = *(const uint4*)(Bg + (size_t)kr * HD + ch * 8);
        uint4 pv1 = *(const uint4*)(Bg + (size_t)kr * HD + 128 + ch * 8);

        for (int it = 0; it < 12; it++) {
            __syncthreads();
            *(uint4*)(smem + bso0) = pv0;
            *(uint4*)(smem + bso1) = pv1;
            __syncthreads();

            if (it < 11) {
                const __nv_bfloat16* brow = Bg + (size_t)((it + 1) * 32 + kr) * HD;
                pv0 = *(const uint4*)(brow + ch * 8);
                pv1 = *(const uint4*)(brow + 128 + ch * 8);
            }

            const int kk = it * 32;
            const int term = kk >> 7;
            const int acolb = (term == 1) ? (128 + (kk & 127)) : (kk & 127);

#pragma unroll
            for (int ks = 0; ks < 32; ks += 16) {
                uint32_t af[2][4];
#pragma unroll
                for (int mi = 0; mi < 2; mi++) {
                    uint32_t addr = sA + a_off(mbase + mi * 16 + a_r, acolb + ks + a_c8);
                    asm volatile("ldmatrix.sync.aligned.m8n8.x4.shared.b16 {%0,%1,%2,%3}, [%4];"
                                 : "=r"(af[mi][0]), "=r"(af[mi][1]), "=r"(af[mi][2]), "=r"(af[mi][3])
                                 : "r"(addr));
                }
                uint32_t bf[4][4];
#pragma unroll
                for (int ni = 0; ni < 4; ni++) {
                    uint32_t addr = sB + b_off(ks + b_kr, nbase + ni * 16 + b_n8);
                    asm volatile("ldmatrix.sync.aligned.m8n8.x4.trans.shared.b16 {%0,%1,%2,%3}, [%4];"
                                 : "=r"(bf[ni][0]), "=r"(bf[ni][1]), "=r"(bf[ni][2]), "=r"(bf[ni][3])
                                 : "r"(addr));
                }
#pragma unroll
                for (int mi = 0; mi < 2; mi++)
#pragma unroll
                    for (int ni = 0; ni < 4; ni++) {
                        asm volatile(
                            "mma.sync.aligned.m16n8k16.row.col.f32.bf16.bf16.f32 "
                            "{%0,%1,%2,%3}, {%4,%5,%6,%7}, {%8,%9}, {%0,%1,%2,%3};"
                            : "+f"(acc[mi][ni*2][0]), "+f"(acc[mi][ni*2][1]),
                              "+f"(acc[mi][ni*2][2]), "+f"(acc[mi][ni*2][3])
                            : "r"(af[mi][0]), "r"(af[mi][1]), "r"(af[mi][2]), "r"(af[mi][3]),
                              "r"(bf[ni][0]), "r"(bf[ni][1]));
                        asm volatile(
                            "mma.sync.aligned.m16n8k16.row.col.f32.bf16.bf16.f32 "
                            "{%0,%1,%2,%3}, {%4,%5,%6,%7}, {%8,%9}, {%0,%1,%2,%3};"
                            : "+f"(acc[mi][ni*2+1][0]), "+f"(acc[mi][ni*2+1][1]),
                              "+f"(acc[mi][ni*2+1][2]), "+f"(acc[mi][ni*2+1][3])
                            : "r"(af[mi][0]), "r"(af[mi][1]), "r"(af[mi][2]), "r"(af[mi][3]),
                              "r"(bf[ni][2]), "r"(bf[ni][3]));
                    }
            }
        }

        const float* bias = mat ? bdst : bsrc;
        float* outp       = mat ? g_fd : g_fs;
#pragma unroll
        for (int mi = 0; mi < 2; mi++) {
#pragma unroll
            for (int n8 = 0; n8 < 8; n8++) {
                int colg = nbase + n8 * 8 + tg * 2;
                float b0 = __ldg(bias + colg);
                float b1 = __ldg(bias + colg + 1);
                int r1 = row0 + mbase + mi * 16 + g;
                int r2 = r1 + 8;
                if (r1 < N_NODES) {
                    float2 v = make_float2(acc[mi][n8][0] + b0, acc[mi][n8][1] + b1);
                    *(float2*)(outp + (size_t)r1 * HD + colg) = v;
                }
                if (r2 < N_NODES) {
                    float2 v = make_float2(acc[mi][n8][2] + b0, acc[mi][n8][3] + b1);
                    *(float2*)(outp + (size_t)r2 * HD + colg) = v;
                }
            }
        }
    }
}

// ---------------- scans ----------------
__global__ __launch_bounds__(256) void k_scan1() {
    __shared__ int sh[256];
    int i = blockIdx.x * 256 + threadIdx.x;
    int v = (i < N_NODES) ? g_deg[i] : 0;
    sh[threadIdx.x] = v;
    __syncthreads();
    for (int d = 1; d < 256; d <<= 1) {
        int t = (threadIdx.x >= d) ? sh[threadIdx.x - d] : 0;
        __syncthreads();
        sh[threadIdx.x] += t;
        __syncthreads();
    }
    if (threadIdx.x == 255) g_blksum[blockIdx.x] = sh[255];
}

__global__ __launch_bounds__(256) void k_scanB() {
    __shared__ int sh[256];
    __shared__ int wsum[8];
    __shared__ int base_s;
    int b = blockIdx.x;
    int t = threadIdx.x;

    int v = (t < b) ? g_blksum[t] : 0;
#pragma unroll
    for (int d = 16; d; d >>= 1) v += __shfl_down_sync(0xFFFFFFFFu, v, d);
    if ((t & 31) == 0) wsum[t >> 5] = v;
    __syncthreads();
    if (t == 0) {
        int s = 0;
#pragma unroll
        for (int j = 0; j < 8; j++) s += wsum[j];
        base_s = s;
    }
    __syncthreads();

    int i = b * 256 + t;
    int dv = (i < N_NODES) ? g_deg[i] : 0;
    sh[t] = dv;
    __syncthreads();
    for (int d = 1; d < 256; d <<= 1) {
        int x = (t >= d) ? sh[t - d] : 0;
        __syncthreads();
        sh[t] += x;
        __syncthreads();
    }
    if (i < N_NODES) g_off[i] = base_s + sh[t] - dv;
}

__global__ __launch_bounds__(256) void k_fill(
    const int* __restrict__ dst, const int* __restrict__ src)
{
    int e = blockIdx.x * blockDim.x + threadIdx.x;
    if (e >= N_EDGES) return;
    int d = dst[e];
    int pos = atomicAdd(&g_cur[d], 1);
    g_epack[g_off[d] + pos] = make_int2(e, src[e]);
}

// ---------------- fused per-node aggregation + score (no-shift softmax) ----------------
__global__ __launch_bounds__(256) void k_agg(
    const float* __restrict__ attn,
    const int* __restrict__ gid, float* __restrict__ x1,
    float* __restrict__ score)
{
    int warp = (blockIdx.x * blockDim.x + threadIdx.x) >> 5;
    if (warp >= N_NODES) return;
    int n = warp;
    int lane = threadIdx.x & 31;
    int base = lane * 8;
    int h = lane >> 3;

    float4 fd0 = *(const float4*)(g_fd + (size_t)n * HD + base);
    float4 fd1 = *(const float4*)(g_fd + (size_t)n * HD + base + 4);
    float4 aw0 = __ldg((const float4*)(attn + base));
    float4 aw1 = __ldg((const float4*)(attn + base + 4));

    int deg = g_deg[n];
    int off = g_off[n];

    float den = 0.0f;
    float acc[8];
#pragma unroll
    for (int j = 0; j < 8; j++) acc[j] = 0.0f;

    // 2-edge unrolled loop: both gathers in flight together
    for (int i = 0; i < deg; i += 2) {
        bool hasB = (i + 1) < deg;
        int2 eA = g_epack[off + i];
        int2 eB = hasB ? g_epack[off + i + 1] : eA;
        const float4* fA = (const float4*)(g_fs + (size_t)eA.y * HD + base);
        const float4* fB = (const float4*)(g_fs + (size_t)eB.y * HD + base);
        float4 a0 = fA[0], a1 = fA[1];
        float4 b0 = fB[0], b1 = fB[1];

        float evA, evB;
        evA  = lrelu(a0.x + fd0.x) * aw0.x;
        evB  = lrelu(b0.x + fd0.x) * aw0.x;
        evA += lrelu(a0.y + fd0.y) * aw0.y;
        evB += lrelu(b0.y + fd0.y) * aw0.y;
        evA += lrelu(a0.z + fd0.z) * aw0.z;
        evB += lrelu(b0.z + fd0.z) * aw0.z;
        evA += lrelu(a0.w + fd0.w) * aw0.w;
        evB += lrelu(b0.w + fd0.w) * aw0.w;
        evA += lrelu(a1.x + fd1.x) * aw1.x;
        evB += lrelu(b1.x + fd1.x) * aw1.x;
        evA += lrelu(a1.y + fd1.y) * aw1.y;
        evB += lrelu(b1.y + fd1.y) * aw1.y;
        evA += lrelu(a1.z + fd1.z) * aw1.z;
        evB += lrelu(b1.z + fd1.z) * aw1.z;
        evA += lrelu(a1.w + fd1.w) * aw1.w;
        evB += lrelu(b1.w + fd1.w) * aw1.w;
#pragma unroll
        for (int d = 1; d < 8; d <<= 1) {
            evA += __shfl_xor_sync(0xFFFFFFFFu, evA, d);
            evB += __shfl_xor_sync(0xFFFFFFFFu, evB, d);
        }

        if ((lane & 7) == 0) {
            g_e[(size_t)eA.x * HEADS + h] = evA;
            if (hasB) g_e[(size_t)eB.x * HEADS + h] = evB;
        }

        // no-shift softmax accumulation (logits bounded; exp safe)
        float exA = __expf(evA);
        float exB = hasB ? __expf(evB) : 0.0f;
        den += exA + exB;
        acc[0] += exA * a0.x + exB * b0.x;
        acc[1] += exA * a0.y + exB * b0.y;
        acc[2] += exA * a0.z + exB * b0.z;
        acc[3] += exA * a0.w + exB * b0.w;
        acc[4] += exA * a1.x + exB * b1.x;
        acc[5] += exA * a1.y + exB * b1.y;
        acc[6] += exA * a1.z + exB * b1.z;
        acc[7] += exA * a1.w + exB * b1.w;
    }

    // ---- node output: rst/den, head mean, graph pool ----
    float inv = (den > 0.0f) ? (1.0f / den) : 0.0f;
    float r[8];
#pragma unroll
    for (int j = 0; j < 8; j++) {
        r[j] = acc[j] * inv;
        r[j] += __shfl_xor_sync(0xFFFFFFFFu, r[j], 8);
        r[j] += __shfl_xor_sync(0xFFFFFFFFu, r[j], 16);
        r[j] *= 0.25f;
    }

    int g = gid[n];
    if (lane < 8) {
        float4 v0 = make_float4(r[0], r[1], r[2], r[3]);
        float4 v1 = make_float4(r[4], r[5], r[6], r[7]);
        float* xp = x1 + (size_t)n * DIM + lane * 8;
        *(float4*)(xp)     = v0;
        *(float4*)(xp + 4) = v1;
        atomicAdd((float4*)(g_hsum + (size_t)g * DIM + lane * 8),     v0);
        atomicAdd((float4*)(g_hsum + (size_t)g * DIM + lane * 8 + 4), v1);
    }
    if (lane == 0) atomicAdd(&g_cnt[g], 1.0f);

    // ---- fused score: alpha = exp(e)/den for this node's edges ----
    if (deg > 0) {
        __threadfence_block();
        __syncwarp();
        int hh = lane & 3;
        float d_h = __shfl_sync(0xFFFFFFFFu, den, hh << 3);
        float dinv = 1.0f / d_h;
        for (int i0 = 0; i0 < deg; i0 += 8) {
            int ei = i0 + (lane >> 2);
            if (ei < deg) {
                int eid = g_epack[off + ei].x;
                float ev = g_e[(size_t)eid * HEADS + hh];
                score[(size_t)eid * HEADS + hh] = __expf(ev) * dinv;
            }
        }
    }
}

// ---------------- graph mean finalize ----------------
__global__ __launch_bounds__(256) void k_final(float* __restrict__ hout)
{
    int idx = blockIdx.x * blockDim.x + threadIdx.x;
    if (idx >= NGRAPHS * DIM) return;
    int g = idx >> 6;
    hout[idx] = g_hsum[idx] / fmaxf(g_cnt[g], 1.0f);
}

// ---------------- launcher ----------------
extern "C" void kernel_launch(void* const* d_in, const int* in_sizes, int n_in,
                              void* d_out, int out_size)
{
    (void)in_sizes; (void)n_in; (void)out_size;

    const float* atom = (const float*)d_in[0];
    const float* Wsrc = (const float*)d_in[1];
    const float* bsrc = (const float*)d_in[2];
    const float* Wdst = (const float*)d_in[3];
    const float* bdst = (const float*)d_in[4];
    const float* attn = (const float*)d_in[5];
    const int*   src  = (const int*)d_in[6];
    const int*   dst  = (const int*)d_in[7];
    const int*   gid  = (const int*)d_in[8];

    float* out   = (float*)d_out;
    float* x1    = out;
    float* hout  = out + (size_t)N_NODES * DIM;
    float* score = hout + (size_t)NGRAPHS * DIM;

    static bool inited = false;
    static cudaStream_t sB;
    static cudaEvent_t evF, evJ;
    if (!inited) {
        cudaStreamCreateWithFlags(&sB, cudaStreamNonBlocking);
        cudaEventCreateWithFlags(&evF, cudaEventDisableTiming);
        cudaEventCreateWithFlags(&evJ, cudaEventDisableTiming);
        inited = true;
    }

    cudaFuncSetAttribute(k_mgemm, cudaFuncAttributeMaxDynamicSharedMemorySize, SM_TOT);

    // prologue on main stream (zeros g_deg needed by hist, builds B_ext for gemm)
    k_pre<<<512, 256>>>(Wsrc, Wdst);

    // fork: CSR chain on sB, GEMM on main stream
    cudaEventRecord(evF, 0);
    cudaStreamWaitEvent(sB, evF, 0);

    int eblocks = (N_EDGES + 255) / 256;
    k_hist <<<eblocks, 256, 0, sB>>>(dst);
    k_scan1<<<SCAN_NB, 256, 0, sB>>>();
    k_scanB<<<SCAN_NB, 256, 0, sB>>>();
    k_fill <<<eblocks, 256, 0, sB>>>(dst, src);
    cudaEventRecord(evJ, sB);

    k_mgemm<<<MBLK, 512, SM_TOT>>>(atom, bsrc, bdst);

    // join: agg needs both GEMM output and CSR
    cudaStreamWaitEvent(0, evJ, 0);

    k_agg<<<(N_NODES * 32 + 255) / 256, 256>>>(attn, gid, x1, score);

    k_final<<<(NGRAPHS * DIM + 255) / 256, 256>>>(hout);
}